// round 2
// baseline (speedup 1.0000x reference)
#include <cuda_runtime.h>
#include <cstdint>

#define N_NODES 100000
#define N_EDGES 800000
#define F_IN    256
#define HID     128
#define CLS     32

// ---------------- scratch (device globals: no allocation allowed) ----------
__device__ float g_deg[N_NODES];
__device__ float g_dinv[N_NODES];
__device__ float g_xw1[(size_t)N_NODES * HID];
__device__ float g_h1 [(size_t)N_NODES * HID];
__device__ float g_xw2[(size_t)N_NODES * CLS];
__device__ int   g_is64;

// ---------------- edge-index dtype probe ------------------------------------
// int64 values < 2^31 have zero odd 32-bit words; int32 random node ids don't.
__global__ void k_detect(const int* __restrict__ ei) {
    if (blockIdx.x == 0 && threadIdx.x == 0) {
        int is64 = 1;
        for (int i = 0; i < 64; i++)
            if (ei[2 * i + 1] != 0) { is64 = 0; break; }
        g_is64 = is64;
    }
}

// which: 0 = src row, 1 = dst row
__device__ __forceinline__ int edge_at(const int* __restrict__ ei,
                                       int which, int e, int is64) {
    size_t base = (size_t)which * N_EDGES + (size_t)e;
    return is64 ? ei[base * 2] : ei[base];
}

// ---------------- degree / norm --------------------------------------------
__global__ void k_init_deg() {
    int i = blockIdx.x * blockDim.x + threadIdx.x;
    if (i < N_NODES) g_deg[i] = 1.0f;   // self-loop contributes 1
}

__global__ void k_deg_scatter(const int* __restrict__ ei) {
    int e = blockIdx.x * blockDim.x + threadIdx.x;
    if (e >= N_EDGES) return;
    int is64 = g_is64;
    int d = edge_at(ei, 1, e, is64);
    atomicAdd(&g_deg[d], 1.0f);
}

__global__ void k_dinv() {
    int i = blockIdx.x * blockDim.x + threadIdx.x;
    if (i < N_NODES) g_dinv[i] = rsqrtf(g_deg[i]);   // deg >= 1 always
}

// ---------------- tiled SGEMM ----------------------------------------------
template<int BM, int BN, int BK, int TM, int TN>
__global__ void sgemm_kernel(const float* __restrict__ A,
                             const float* __restrict__ B,
                             float* __restrict__ C,
                             int M, int N, int K) {
    constexpr int THREADS = (BM / TM) * (BN / TN);
    __shared__ float As[BK][BM];
    __shared__ float Bs[BK][BN];

    const int tid = threadIdx.x;
    const int tx  = tid % (BN / TN);
    const int ty  = tid / (BN / TN);
    const int rowBase = blockIdx.y * BM;
    const int colBase = blockIdx.x * BN;

    float acc[TM][TN];
#pragma unroll
    for (int i = 0; i < TM; i++)
#pragma unroll
        for (int j = 0; j < TN; j++) acc[i][j] = 0.0f;

    for (int kt = 0; kt < K; kt += BK) {
        // load A tile (transposed into As[k][m]) — float4 loads
#pragma unroll
        for (int idx = tid; idx < BM * BK / 4; idx += THREADS) {
            int r = idx / (BK / 4);
            int c = (idx % (BK / 4)) * 4;
            int gr = rowBase + r;
            float4 v = make_float4(0.f, 0.f, 0.f, 0.f);
            if (gr < M) v = *(const float4*)(A + (size_t)gr * K + kt + c);
            As[c + 0][r] = v.x; As[c + 1][r] = v.y;
            As[c + 2][r] = v.z; As[c + 3][r] = v.w;
        }
        // load B tile
#pragma unroll
        for (int idx = tid; idx < BK * BN / 4; idx += THREADS) {
            int r = idx / (BN / 4);
            int c = (idx % (BN / 4)) * 4;
            int gc = colBase + c;
            float4 v = make_float4(0.f, 0.f, 0.f, 0.f);
            if (gc < N) v = *(const float4*)(B + (size_t)(kt + r) * N + gc);
            *(float4*)&Bs[r][c] = v;
        }
        __syncthreads();

#pragma unroll
        for (int k = 0; k < BK; k++) {
            float ra[TM], rb[TN];
#pragma unroll
            for (int i = 0; i < TM; i++) ra[i] = As[k][ty * TM + i];
#pragma unroll
            for (int j = 0; j < TN; j++) rb[j] = Bs[k][tx * TN + j];
#pragma unroll
            for (int i = 0; i < TM; i++)
#pragma unroll
                for (int j = 0; j < TN; j++)
                    acc[i][j] += ra[i] * rb[j];
        }
        __syncthreads();
    }

#pragma unroll
    for (int i = 0; i < TM; i++) {
        int gr = rowBase + ty * TM + i;
        if (gr >= M) continue;
#pragma unroll
        for (int j = 0; j < TN; j++) {
            int gc = colBase + tx * TN + j;
            if (gc < N) C[(size_t)gr * N + gc] = acc[i][j];
        }
    }
}

// ---------------- layer-1 aggregation ---------------------------------------
// init: h1[i,:] = xw1[i,:] * dinv[i]^2  (the self-loop term)
__global__ void k_init_h1() {
    size_t i = (size_t)blockIdx.x * blockDim.x + threadIdx.x;
    if (i >= (size_t)N_NODES * HID / 4) return;
    int node = (int)(i / (HID / 4));
    float s = g_dinv[node]; s = s * s;
    float4 v = ((const float4*)g_xw1)[i];
    v.x *= s; v.y *= s; v.z *= s; v.w *= s;
    ((float4*)g_h1)[i] = v;
}

// one warp per edge; lane handles 4 columns (32*4 = 128)
__global__ void k_scatter1(const int* __restrict__ ei) {
    int w    = (blockIdx.x * blockDim.x + threadIdx.x) >> 5;
    int lane = threadIdx.x & 31;
    if (w >= N_EDGES) return;
    int is64 = g_is64;
    int s = edge_at(ei, 0, w, is64);
    int d = edge_at(ei, 1, w, is64);
    float nrm = g_dinv[s] * g_dinv[d];
    float4 v = ((const float4*)(g_xw1 + (size_t)s * HID))[lane];
    float* hd = g_h1 + (size_t)d * HID + lane * 4;
    atomicAdd(hd + 0, v.x * nrm);
    atomicAdd(hd + 1, v.y * nrm);
    atomicAdd(hd + 2, v.z * nrm);
    atomicAdd(hd + 3, v.w * nrm);
}

__global__ void k_relu_bias(const float* __restrict__ b1) {
    size_t i = (size_t)blockIdx.x * blockDim.x + threadIdx.x;
    if (i >= (size_t)N_NODES * HID / 4) return;
    int c4 = (int)(i % (HID / 4));
    float4 b = ((const float4*)b1)[c4];
    float4 v = ((float4*)g_h1)[i];
    v.x = fmaxf(v.x + b.x, 0.f);
    v.y = fmaxf(v.y + b.y, 0.f);
    v.z = fmaxf(v.z + b.z, 0.f);
    v.w = fmaxf(v.w + b.w, 0.f);
    ((float4*)g_h1)[i] = v;
}

// ---------------- layer-2 aggregation ---------------------------------------
__global__ void k_init_out(float* __restrict__ out) {
    size_t i = (size_t)blockIdx.x * blockDim.x + threadIdx.x;
    if (i >= (size_t)N_NODES * CLS / 4) return;
    int node = (int)(i / (CLS / 4));
    float s = g_dinv[node]; s = s * s;
    float4 v = ((const float4*)g_xw2)[i];
    v.x *= s; v.y *= s; v.z *= s; v.w *= s;
    ((float4*)out)[i] = v;
}

// one warp per edge; lane = class index (CLS == 32)
__global__ void k_scatter2(const int* __restrict__ ei,
                           float* __restrict__ out) {
    int w    = (blockIdx.x * blockDim.x + threadIdx.x) >> 5;
    int lane = threadIdx.x & 31;
    if (w >= N_EDGES) return;
    int is64 = g_is64;
    int s = edge_at(ei, 0, w, is64);
    int d = edge_at(ei, 1, w, is64);
    float nrm = g_dinv[s] * g_dinv[d];
    float v = g_xw2[(size_t)s * CLS + lane] * nrm;
    atomicAdd(&out[(size_t)d * CLS + lane], v);
}

// ---------------- bias + log_softmax (warp per row) -------------------------
__global__ void k_logsoftmax(const float* __restrict__ b2,
                             float* __restrict__ out) {
    int row  = blockIdx.x * (blockDim.x >> 5) + (threadIdx.x >> 5);
    int lane = threadIdx.x & 31;
    if (row >= N_NODES) return;
    float v = out[(size_t)row * CLS + lane] + b2[lane];
    float m = v;
#pragma unroll
    for (int o = 16; o > 0; o >>= 1) m = fmaxf(m, __shfl_xor_sync(0xffffffffu, m, o));
    float e = __expf(v - m);
    float ssum = e;
#pragma unroll
    for (int o = 16; o > 0; o >>= 1) ssum += __shfl_xor_sync(0xffffffffu, ssum, o);
    out[(size_t)row * CLS + lane] = v - m - __logf(ssum);
}

// ---------------- launch -----------------------------------------------------
extern "C" void kernel_launch(void* const* d_in, const int* in_sizes, int n_in,
                              void* d_out, int out_size) {
    const float* X   = (const float*)d_in[0];
    const int*   ei  = (const int*)d_in[1];   // int32 node ids, or int64 probed at runtime
    const float* W1  = (const float*)d_in[2];
    const float* b1  = (const float*)d_in[3];
    const float* W2  = (const float*)d_in[4];
    const float* b2  = (const float*)d_in[5];
    float*       out = (float*)d_out;

    // device-global scratch addresses (not stream ops; capture-safe)
    float *p_xw1 = nullptr, *p_h1 = nullptr, *p_xw2 = nullptr;
    cudaGetSymbolAddress((void**)&p_xw1, g_xw1);
    cudaGetSymbolAddress((void**)&p_h1,  g_h1);
    cudaGetSymbolAddress((void**)&p_xw2, g_xw2);

    const int TB = 256;

    // probe edge dtype, then degree + norm
    k_detect     <<<1, 32>>>(ei);
    k_init_deg   <<<(N_NODES + TB - 1) / TB, TB>>>();
    k_deg_scatter<<<(N_EDGES + TB - 1) / TB, TB>>>(ei);
    k_dinv       <<<(N_NODES + TB - 1) / TB, TB>>>();

    // layer 1: xw1 = X @ W1
    {
        dim3 grid(HID / 128, (N_NODES + 127) / 128);
        sgemm_kernel<128, 128, 16, 8, 8><<<grid, 256>>>(X, W1, p_xw1,
                                                        N_NODES, HID, F_IN);
    }
    k_init_h1 <<<((size_t)N_NODES * HID / 4 + TB - 1) / TB, TB>>>();
    k_scatter1<<<(size_t)N_EDGES * 32 / TB, TB>>>(ei);
    k_relu_bias<<<((size_t)N_NODES * HID / 4 + TB - 1) / TB, TB>>>(b1);

    // layer 2: xw2 = h1 @ W2
    {
        dim3 grid(CLS / 32, (N_NODES + 127) / 128);
        sgemm_kernel<128, 32, 32, 8, 2><<<grid, 256>>>(p_h1, W2, p_xw2,
                                                       N_NODES, CLS, HID);
    }
    k_init_out<<<((size_t)N_NODES * CLS / 4 + TB - 1) / TB, TB>>>(out);
    k_scatter2<<<(size_t)N_EDGES * 32 / TB, TB>>>(ei, out);
    k_logsoftmax<<<(N_NODES + 7) / 8, 256>>>(b2, out);
}

// round 3
// speedup vs baseline: 1.2384x; 1.2384x over previous
#include <cuda_runtime.h>
#include <cstdint>

#define N_NODES 100000
#define N_EDGES 800000
#define F_IN    256
#define HID     128
#define CLS     32

// ---------------- scratch (device globals: no allocation allowed) ----------
__device__ float g_deg[N_NODES];
__device__ float g_dinv[N_NODES];
__device__ float g_xw1[(size_t)N_NODES * HID];
__device__ float g_h1 [(size_t)N_NODES * HID];
__device__ float g_xw2[(size_t)N_NODES * CLS];
__device__ int   g_is64;

// ---------------- vector reduction (sm_90+) ---------------------------------
__device__ __forceinline__ void red_add_v4(float* addr, float4 v) {
    asm volatile("red.global.v4.f32.add [%0], {%1,%2,%3,%4};"
                 :: "l"(addr), "f"(v.x), "f"(v.y), "f"(v.z), "f"(v.w)
                 : "memory");
}

// ---------------- edge-index dtype probe ------------------------------------
// int64 values < 2^31 have zero odd 32-bit words; int32 random node ids don't.
__global__ void k_detect(const int* __restrict__ ei) {
    if (blockIdx.x == 0 && threadIdx.x == 0) {
        int is64 = 1;
        for (int i = 0; i < 64; i++)
            if (ei[2 * i + 1] != 0) { is64 = 0; break; }
        g_is64 = is64;
    }
}

// which: 0 = src row, 1 = dst row
__device__ __forceinline__ int edge_at(const int* __restrict__ ei,
                                       int which, int e, int is64) {
    size_t base = (size_t)which * N_EDGES + (size_t)e;
    return is64 ? ei[base * 2] : ei[base];
}

// ---------------- degree / norm --------------------------------------------
__global__ void k_init_deg() {
    int i = blockIdx.x * blockDim.x + threadIdx.x;
    if (i < N_NODES) g_deg[i] = 1.0f;   // self-loop contributes 1
}

__global__ void k_deg_scatter(const int* __restrict__ ei) {
    int e = blockIdx.x * blockDim.x + threadIdx.x;
    if (e >= N_EDGES) return;
    int is64 = g_is64;
    int d = edge_at(ei, 1, e, is64);
    atomicAdd(&g_deg[d], 1.0f);
}

__global__ void k_dinv() {
    int i = blockIdx.x * blockDim.x + threadIdx.x;
    if (i < N_NODES) g_dinv[i] = rsqrtf(g_deg[i]);   // deg >= 1 always
}

// ---------------- tiled SGEMM with fused self-loop epilogue -----------------
// C  = A @ B
// C2 = C * dinv[row]^2   (self-loop init of the aggregation buffer)
template<int BM, int BN, int BK, int TM, int TN>
__global__ void sgemm_kernel(const float* __restrict__ A,
                             const float* __restrict__ B,
                             float* __restrict__ C,
                             float* __restrict__ C2,
                             const float* __restrict__ dinv,
                             int M, int N, int K) {
    constexpr int THREADS = (BM / TM) * (BN / TN);
    __shared__ float As[BK][BM];
    __shared__ float Bs[BK][BN];

    const int tid = threadIdx.x;
    const int tx  = tid % (BN / TN);
    const int ty  = tid / (BN / TN);
    const int rowBase = blockIdx.y * BM;
    const int colBase = blockIdx.x * BN;

    float acc[TM][TN];
#pragma unroll
    for (int i = 0; i < TM; i++)
#pragma unroll
        for (int j = 0; j < TN; j++) acc[i][j] = 0.0f;

    for (int kt = 0; kt < K; kt += BK) {
#pragma unroll
        for (int idx = tid; idx < BM * BK / 4; idx += THREADS) {
            int r = idx / (BK / 4);
            int c = (idx % (BK / 4)) * 4;
            int gr = rowBase + r;
            float4 v = make_float4(0.f, 0.f, 0.f, 0.f);
            if (gr < M) v = *(const float4*)(A + (size_t)gr * K + kt + c);
            As[c + 0][r] = v.x; As[c + 1][r] = v.y;
            As[c + 2][r] = v.z; As[c + 3][r] = v.w;
        }
#pragma unroll
        for (int idx = tid; idx < BK * BN / 4; idx += THREADS) {
            int r = idx / (BN / 4);
            int c = (idx % (BN / 4)) * 4;
            int gc = colBase + c;
            float4 v = make_float4(0.f, 0.f, 0.f, 0.f);
            if (gc < N) v = *(const float4*)(B + (size_t)(kt + r) * N + gc);
            *(float4*)&Bs[r][c] = v;
        }
        __syncthreads();

#pragma unroll
        for (int k = 0; k < BK; k++) {
            float ra[TM], rb[TN];
#pragma unroll
            for (int i = 0; i < TM; i++) ra[i] = As[k][ty * TM + i];
#pragma unroll
            for (int j = 0; j < TN; j++) rb[j] = Bs[k][tx * TN + j];
#pragma unroll
            for (int i = 0; i < TM; i++)
#pragma unroll
                for (int j = 0; j < TN; j++)
                    acc[i][j] += ra[i] * rb[j];
        }
        __syncthreads();
    }

#pragma unroll
    for (int i = 0; i < TM; i++) {
        int gr = rowBase + ty * TM + i;
        if (gr >= M) continue;
        float s = dinv[gr]; s = s * s;
#pragma unroll
        for (int j = 0; j < TN; j++) {
            int gc = colBase + tx * TN + j;
            if (gc < N) {
                C [(size_t)gr * N + gc] = acc[i][j];
                C2[(size_t)gr * N + gc] = acc[i][j] * s;
            }
        }
    }
}

// ---------------- layer-1 edge scatter (warp/edge, v4 reductions) -----------
__global__ void k_scatter1(const int* __restrict__ ei) {
    int w    = (blockIdx.x * blockDim.x + threadIdx.x) >> 5;
    int lane = threadIdx.x & 31;
    if (w >= N_EDGES) return;
    int is64 = g_is64;
    int s = edge_at(ei, 0, w, is64);
    int d = edge_at(ei, 1, w, is64);
    float nrm = g_dinv[s] * g_dinv[d];
    float4 v = ((const float4*)(g_xw1 + (size_t)s * HID))[lane];
    v.x *= nrm; v.y *= nrm; v.z *= nrm; v.w *= nrm;
    red_add_v4(g_h1 + (size_t)d * HID + lane * 4, v);
}

__global__ void k_relu_bias(const float* __restrict__ b1) {
    size_t i = (size_t)blockIdx.x * blockDim.x + threadIdx.x;
    if (i >= (size_t)N_NODES * HID / 4) return;
    int c4 = (int)(i % (HID / 4));
    float4 b = ((const float4*)b1)[c4];
    float4 v = ((float4*)g_h1)[i];
    v.x = fmaxf(v.x + b.x, 0.f);
    v.y = fmaxf(v.y + b.y, 0.f);
    v.z = fmaxf(v.z + b.z, 0.f);
    v.w = fmaxf(v.w + b.w, 0.f);
    ((float4*)g_h1)[i] = v;
}

// ---------------- layer-2 edge scatter (8 lanes/edge, v4 reductions) --------
__global__ void k_scatter2(const int* __restrict__ ei,
                           float* __restrict__ out) {
    size_t t = (size_t)blockIdx.x * blockDim.x + threadIdx.x;
    int e   = (int)(t >> 3);
    int sub = (int)(t & 7);
    if (e >= N_EDGES) return;
    int is64 = g_is64;
    int s = edge_at(ei, 0, e, is64);
    int d = edge_at(ei, 1, e, is64);
    float nrm = g_dinv[s] * g_dinv[d];
    float4 v = ((const float4*)(g_xw2 + (size_t)s * CLS))[sub];
    v.x *= nrm; v.y *= nrm; v.z *= nrm; v.w *= nrm;
    red_add_v4(out + (size_t)d * CLS + sub * 4, v);
}

// ---------------- bias + log_softmax (warp per row) -------------------------
__global__ void k_logsoftmax(const float* __restrict__ b2,
                             float* __restrict__ out) {
    int row  = blockIdx.x * (blockDim.x >> 5) + (threadIdx.x >> 5);
    int lane = threadIdx.x & 31;
    if (row >= N_NODES) return;
    float v = out[(size_t)row * CLS + lane] + b2[lane];
    float m = v;
#pragma unroll
    for (int o = 16; o > 0; o >>= 1) m = fmaxf(m, __shfl_xor_sync(0xffffffffu, m, o));
    float e = __expf(v - m);
    float ssum = e;
#pragma unroll
    for (int o = 16; o > 0; o >>= 1) ssum += __shfl_xor_sync(0xffffffffu, ssum, o);
    out[(size_t)row * CLS + lane] = v - m - __logf(ssum);
}

// ---------------- launch -----------------------------------------------------
extern "C" void kernel_launch(void* const* d_in, const int* in_sizes, int n_in,
                              void* d_out, int out_size) {
    const float* X   = (const float*)d_in[0];
    const int*   ei  = (const int*)d_in[1];   // int32 node ids, or int64 (probed)
    const float* W1  = (const float*)d_in[2];
    const float* b1  = (const float*)d_in[3];
    const float* W2  = (const float*)d_in[4];
    const float* b2  = (const float*)d_in[5];
    float*       out = (float*)d_out;

    float *p_xw1 = nullptr, *p_h1 = nullptr, *p_xw2 = nullptr, *p_dinv = nullptr;
    cudaGetSymbolAddress((void**)&p_xw1,  g_xw1);
    cudaGetSymbolAddress((void**)&p_h1,   g_h1);
    cudaGetSymbolAddress((void**)&p_xw2,  g_xw2);
    cudaGetSymbolAddress((void**)&p_dinv, g_dinv);

    const int TB = 256;

    // probe edge dtype, then degree + norm
    k_detect     <<<1, 32>>>(ei);
    k_init_deg   <<<(N_NODES + TB - 1) / TB, TB>>>();
    k_deg_scatter<<<(N_EDGES + TB - 1) / TB, TB>>>(ei);
    k_dinv       <<<(N_NODES + TB - 1) / TB, TB>>>();

    // layer 1: xw1 = X @ W1 ; h1 = xw1 * dinv^2 (fused epilogue)
    {
        dim3 grid(HID / 128, (N_NODES + 127) / 128);
        sgemm_kernel<128, 128, 16, 8, 8><<<grid, 256>>>(X, W1, p_xw1, p_h1,
                                                        p_dinv, N_NODES, HID, F_IN);
    }
    k_scatter1 <<<(size_t)N_EDGES * 32 / TB, TB>>>(ei);
    k_relu_bias<<<((size_t)N_NODES * HID / 4 + TB - 1) / TB, TB>>>(b1);

    // layer 2: xw2 = h1 @ W2 ; out = xw2 * dinv^2 (fused epilogue)
    {
        dim3 grid(CLS / 32, (N_NODES + 127) / 128);
        sgemm_kernel<128, 32, 32, 8, 2><<<grid, 256>>>(p_h1, W2, p_xw2, out,
                                                       p_dinv, N_NODES, CLS, HID);
    }
    k_scatter2  <<<((size_t)N_EDGES * 8 + TB - 1) / TB, TB>>>(ei, out);
    k_logsoftmax<<<(N_NODES + 7) / 8, 256>>>(b2, out);
}

// round 5
// speedup vs baseline: 1.8791x; 1.5174x over previous
#include <cuda_runtime.h>
#include <cuda_bf16.h>
#include <cstdint>

#define N_NODES 100000
#define N_EDGES 800000
#define F_IN    256
#define HID     128
#define CLS     32

// ---------------- scratch (device globals: no allocation allowed) ----------
__device__ float g_deg[N_NODES];
__device__ float g_dinv[N_NODES];
__device__ float g_q1 [(size_t)N_NODES * HID];   // xw1 * dinv[row]
__device__ float g_h1 [(size_t)N_NODES * HID];   // aggregation buffer
__device__ float g_q2 [(size_t)N_NODES * CLS];   // xw2 * dinv[row]
__device__ int   g_is64;

// ---------------- helpers ----------------------------------------------------
__device__ __forceinline__ void red_add_v4(float* addr, float4 v) {
    asm volatile("red.global.v4.f32.add [%0], {%1,%2,%3,%4};"
                 :: "l"(addr), "f"(v.x), "f"(v.y), "f"(v.z), "f"(v.w)
                 : "memory");
}
__device__ __forceinline__ uint32_t smem_addr(const void* p) {
    return (uint32_t)__cvta_generic_to_shared(p);
}

#define LDSM_X4(r, a)                                                          \
    asm volatile("ldmatrix.sync.aligned.m8n8.x4.shared.b16 {%0,%1,%2,%3}, [%4];" \
                 : "=r"((r)[0]), "=r"((r)[1]), "=r"((r)[2]), "=r"((r)[3])      \
                 : "r"(a))
#define LDSM_X2T(r, a)                                                         \
    asm volatile("ldmatrix.sync.aligned.m8n8.x2.trans.shared.b16 {%0,%1}, [%2];" \
                 : "=r"((r)[0]), "=r"((r)[1]) : "r"(a))
#define MMA_BF16(c, a, b)                                                      \
    asm volatile("mma.sync.aligned.m16n8k16.row.col.f32.bf16.bf16.f32 "        \
                 "{%0,%1,%2,%3}, {%4,%5,%6,%7}, {%8,%9}, {%0,%1,%2,%3};"       \
                 : "+f"((c)[0]), "+f"((c)[1]), "+f"((c)[2]), "+f"((c)[3])      \
                 : "r"((a)[0]), "r"((a)[1]), "r"((a)[2]), "r"((a)[3]),         \
                   "r"((b)[0]), "r"((b)[1]))

// ---------------- edge-index dtype probe ------------------------------------
__global__ void k_detect(const int* __restrict__ ei) {
    if (blockIdx.x == 0 && threadIdx.x == 0) {
        int is64 = 1;
        for (int i = 0; i < 64; i++)
            if (ei[2 * i + 1] != 0) { is64 = 0; break; }
        g_is64 = is64;
    }
}
__device__ __forceinline__ int edge_at(const int* __restrict__ ei,
                                       int which, int e, int is64) {
    size_t base = (size_t)which * N_EDGES + (size_t)e;
    return is64 ? ei[base * 2] : ei[base];
}

// ---------------- degree / norm ---------------------------------------------
__global__ void k_init_deg() {
    int i = blockIdx.x * blockDim.x + threadIdx.x;
    if (i < N_NODES) g_deg[i] = 1.0f;
}
__global__ void k_deg_scatter(const int* __restrict__ ei) {
    int e = blockIdx.x * blockDim.x + threadIdx.x;
    if (e >= N_EDGES) return;
    atomicAdd(&g_deg[edge_at(ei, 1, e, g_is64)], 1.0f);
}
__global__ void k_dinv() {
    int i = blockIdx.x * blockDim.x + threadIdx.x;
    if (i < N_NODES) g_dinv[i] = rsqrtf(g_deg[i]);
}

// ---------------- layer-1 GEMM: mma.sync bf16-split (3xMMA) -----------------
// D = X[128t,256] @ W1[256,128]; q1 = D*dinv[row]; h1 = D*dinv[row]^2
#define BM 128
#define BN 128
#define BK 32
#define APAD 8
#define BPAD 8

__global__ __launch_bounds__(256, 1) void gemm1_mma(const float* __restrict__ X,
                                                    const float* __restrict__ W1) {
    __shared__ __align__(16) __nv_bfloat16 sAh[BM][BK + APAD];
    __shared__ __align__(16) __nv_bfloat16 sAl[BM][BK + APAD];
    __shared__ __align__(16) __nv_bfloat16 sBh[BK][BN + BPAD];
    __shared__ __align__(16) __nv_bfloat16 sBl[BK][BN + BPAD];

    const int tid  = threadIdx.x;
    const int lane = tid & 31;
    const int wid  = tid >> 5;
    const int wm   = wid >> 2;       // 0..1  (64 rows each)
    const int wn   = wid & 3;        // 0..3  (32 cols each)
    const int rowBase = blockIdx.x * BM;

    float acc[4][4][4];
#pragma unroll
    for (int mi = 0; mi < 4; mi++)
#pragma unroll
        for (int ni = 0; ni < 4; ni++)
#pragma unroll
            for (int r = 0; r < 4; r++) acc[mi][ni][r] = 0.f;

    for (int kt = 0; kt < F_IN; kt += BK) {
        // ---- A tile: X[rowBase..+128, kt..+32) -> bf16 hi/lo ----
#pragma unroll
        for (int i = 0; i < 4; i++) {
            int idx = tid + i * 256;           // 1024 float4 slots
            int r = idx >> 3, c4 = (idx & 7) * 4;
            int gr = rowBase + r;
            float4 v = make_float4(0.f, 0.f, 0.f, 0.f);
            if (gr < N_NODES)
                v = *(const float4*)(X + (size_t)gr * F_IN + kt + c4);
#pragma unroll
            for (int j = 0; j < 4; j++) {
                float x = (&v.x)[j];
                __nv_bfloat16 hi = __float2bfloat16(x);
                __nv_bfloat16 lo = __float2bfloat16(x - __bfloat162float(hi));
                sAh[r][c4 + j] = hi;
                sAl[r][c4 + j] = lo;
            }
        }
        // ---- B tile: W1[kt..+32, 0..128) -> bf16 hi/lo ----
#pragma unroll
        for (int i = 0; i < 4; i++) {
            int idx = tid + i * 256;           // 1024 float4 slots
            int k = idx >> 5, n4 = (idx & 31) * 4;
            float4 w = *(const float4*)(W1 + (size_t)(kt + k) * HID + n4);
#pragma unroll
            for (int j = 0; j < 4; j++) {
                float x = (&w.x)[j];
                __nv_bfloat16 hi = __float2bfloat16(x);
                __nv_bfloat16 lo = __float2bfloat16(x - __bfloat162float(hi));
                sBh[k][n4 + j] = hi;
                sBl[k][n4 + j] = lo;
            }
        }
        __syncthreads();

#pragma unroll
        for (int ks = 0; ks < BK / 16; ks++) {
            int k16 = ks * 16;
            uint32_t ah[4][4], al[4][4], bh[4][2], bl[4][2];
#pragma unroll
            for (int mi = 0; mi < 4; mi++) {
                int row = wm * 64 + mi * 16 + (lane & 15);
                int col = k16 + (lane >> 4) * 8;
                LDSM_X4(ah[mi], smem_addr(&sAh[row][col]));
                LDSM_X4(al[mi], smem_addr(&sAl[row][col]));
            }
#pragma unroll
            for (int ni = 0; ni < 4; ni++) {
                int krow = k16 + (lane & 15);
                int col  = wn * 32 + ni * 8;
                LDSM_X2T(bh[ni], smem_addr(&sBh[krow][col]));
                LDSM_X2T(bl[ni], smem_addr(&sBl[krow][col]));
            }
#pragma unroll
            for (int mi = 0; mi < 4; mi++)
#pragma unroll
                for (int ni = 0; ni < 4; ni++) {
                    MMA_BF16(acc[mi][ni], ah[mi], bh[ni]);
                    MMA_BF16(acc[mi][ni], ah[mi], bl[ni]);
                    MMA_BF16(acc[mi][ni], al[mi], bh[ni]);
                }
        }
        __syncthreads();
    }

    // ---- epilogue: q1 = D*dinv, h1 = D*dinv^2 ----
    const int rBase = rowBase + wm * 64 + (lane >> 2);
    const int cBase = wn * 32 + (lane & 3) * 2;
#pragma unroll
    for (int mi = 0; mi < 4; mi++) {
        int gr0 = rBase + mi * 16;
        int gr1 = gr0 + 8;
        float d0 = 0.f, d1 = 0.f;
        if (gr0 < N_NODES) d0 = g_dinv[gr0];
        if (gr1 < N_NODES) d1 = g_dinv[gr1];
#pragma unroll
        for (int ni = 0; ni < 4; ni++) {
            int gc = cBase + ni * 8;
            if (gr0 < N_NODES) {
                float2 q = make_float2(acc[mi][ni][0] * d0, acc[mi][ni][1] * d0);
                float2 h = make_float2(q.x * d0, q.y * d0);
                *(float2*)(g_q1 + (size_t)gr0 * HID + gc) = q;
                *(float2*)(g_h1 + (size_t)gr0 * HID + gc) = h;
            }
            if (gr1 < N_NODES) {
                float2 q = make_float2(acc[mi][ni][2] * d1, acc[mi][ni][3] * d1);
                float2 h = make_float2(q.x * d1, q.y * d1);
                *(float2*)(g_q1 + (size_t)gr1 * HID + gc) = q;
                *(float2*)(g_h1 + (size_t)gr1 * HID + gc) = h;
            }
        }
    }
}

// ---------------- SIMT SGEMM layer 2 with fused epilogue --------------------
template<int TBM, int TBN, int TBK, int TM, int TN>
__global__ void sgemm2_kernel(const float* __restrict__ A,
                              const float* __restrict__ B,
                              float* __restrict__ Q,
                              float* __restrict__ O,
                              const float* __restrict__ dinv,
                              int M, int N, int K) {
    constexpr int THREADS = (TBM / TM) * (TBN / TN);
    __shared__ float As[TBK][TBM];
    __shared__ float Bs[TBK][TBN];

    const int tid = threadIdx.x;
    const int tx  = tid % (TBN / TN);
    const int ty  = tid / (TBN / TN);
    const int rowBase = blockIdx.y * TBM;
    const int colBase = blockIdx.x * TBN;

    float acc[TM][TN];
#pragma unroll
    for (int i = 0; i < TM; i++)
#pragma unroll
        for (int j = 0; j < TN; j++) acc[i][j] = 0.0f;

    for (int kt = 0; kt < K; kt += TBK) {
#pragma unroll
        for (int idx = tid; idx < TBM * TBK / 4; idx += THREADS) {
            int r = idx / (TBK / 4);
            int c = (idx % (TBK / 4)) * 4;
            int gr = rowBase + r;
            float4 v = make_float4(0.f, 0.f, 0.f, 0.f);
            if (gr < M) v = *(const float4*)(A + (size_t)gr * K + kt + c);
            As[c + 0][r] = v.x; As[c + 1][r] = v.y;
            As[c + 2][r] = v.z; As[c + 3][r] = v.w;
        }
#pragma unroll
        for (int idx = tid; idx < TBK * TBN / 4; idx += THREADS) {
            int r = idx / (TBN / 4);
            int c = (idx % (TBN / 4)) * 4;
            int gc = colBase + c;
            float4 v = make_float4(0.f, 0.f, 0.f, 0.f);
            if (gc < N) v = *(const float4*)(B + (size_t)(kt + r) * N + gc);
            *(float4*)&Bs[r][c] = v;
        }
        __syncthreads();
#pragma unroll
        for (int k = 0; k < TBK; k++) {
            float ra[TM], rb[TN];
#pragma unroll
            for (int i = 0; i < TM; i++) ra[i] = As[k][ty * TM + i];
#pragma unroll
            for (int j = 0; j < TN; j++) rb[j] = Bs[k][tx * TN + j];
#pragma unroll
            for (int i = 0; i < TM; i++)
#pragma unroll
                for (int j = 0; j < TN; j++)
                    acc[i][j] += ra[i] * rb[j];
        }
        __syncthreads();
    }

#pragma unroll
    for (int i = 0; i < TM; i++) {
        int gr = rowBase + ty * TM + i;
        if (gr >= M) continue;
        float d = dinv[gr], d2 = d * d;
#pragma unroll
        for (int j = 0; j < TN; j++) {
            int gc = colBase + tx * TN + j;
            if (gc < N) {
                Q[(size_t)gr * N + gc] = acc[i][j] * d;
                O[(size_t)gr * N + gc] = acc[i][j] * d2;
            }
        }
    }
}

// ---------------- edge scatters ---------------------------------------------
__global__ void k_scatter1(const int* __restrict__ ei) {
    int w    = (blockIdx.x * blockDim.x + threadIdx.x) >> 5;
    int lane = threadIdx.x & 31;
    if (w >= N_EDGES) return;
    int is64 = g_is64;
    int s = edge_at(ei, 0, w, is64);
    int d = edge_at(ei, 1, w, is64);
    float nrm = g_dinv[d];
    float4 v = ((const float4*)(g_q1 + (size_t)s * HID))[lane];
    v.x *= nrm; v.y *= nrm; v.z *= nrm; v.w *= nrm;
    red_add_v4(g_h1 + (size_t)d * HID + lane * 4, v);
}

__global__ void k_relu_bias(const float* __restrict__ b1) {
    size_t i = (size_t)blockIdx.x * blockDim.x + threadIdx.x;
    if (i >= (size_t)N_NODES * HID / 4) return;
    int c4 = (int)(i % (HID / 4));
    float4 b = ((const float4*)b1)[c4];
    float4 v = ((float4*)g_h1)[i];
    v.x = fmaxf(v.x + b.x, 0.f);
    v.y = fmaxf(v.y + b.y, 0.f);
    v.z = fmaxf(v.z + b.z, 0.f);
    v.w = fmaxf(v.w + b.w, 0.f);
    ((float4*)g_h1)[i] = v;
}

__global__ void k_scatter2(const int* __restrict__ ei,
                           float* __restrict__ out) {
    size_t t = (size_t)blockIdx.x * blockDim.x + threadIdx.x;
    int e   = (int)(t >> 3);
    int sub = (int)(t & 7);
    if (e >= N_EDGES) return;
    int is64 = g_is64;
    int s = edge_at(ei, 0, e, is64);
    int d = edge_at(ei, 1, e, is64);
    float nrm = g_dinv[d];
    float4 v = ((const float4*)(g_q2 + (size_t)s * CLS))[sub];
    v.x *= nrm; v.y *= nrm; v.z *= nrm; v.w *= nrm;
    red_add_v4(out + (size_t)d * CLS + sub * 4, v);
}

// ---------------- bias + log_softmax ----------------------------------------
__global__ void k_logsoftmax(const float* __restrict__ b2,
                             float* __restrict__ out) {
    int row  = blockIdx.x * (blockDim.x >> 5) + (threadIdx.x >> 5);
    int lane = threadIdx.x & 31;
    if (row >= N_NODES) return;
    float v = out[(size_t)row * CLS + lane] + b2[lane];
    float m = v;
#pragma unroll
    for (int o = 16; o > 0; o >>= 1) m = fmaxf(m, __shfl_xor_sync(0xffffffffu, m, o));
    float e = __expf(v - m);
    float ssum = e;
#pragma unroll
    for (int o = 16; o > 0; o >>= 1) ssum += __shfl_xor_sync(0xffffffffu, ssum, o);
    out[(size_t)row * CLS + lane] = v - m - __logf(ssum);
}

// ---------------- launch -----------------------------------------------------
extern "C" void kernel_launch(void* const* d_in, const int* in_sizes, int n_in,
                              void* d_out, int out_size) {
    const float* X   = (const float*)d_in[0];
    const int*   ei  = (const int*)d_in[1];
    const float* W1  = (const float*)d_in[2];
    const float* b1  = (const float*)d_in[3];
    const float* W2  = (const float*)d_in[4];
    const float* b2  = (const float*)d_in[5];
    float*       out = (float*)d_out;

    float *p_h1 = nullptr, *p_q2 = nullptr, *p_dinv = nullptr;
    cudaGetSymbolAddress((void**)&p_h1,   g_h1);
    cudaGetSymbolAddress((void**)&p_q2,   g_q2);
    cudaGetSymbolAddress((void**)&p_dinv, g_dinv);

    const int TB = 256;

    k_detect     <<<1, 32>>>(ei);
    k_init_deg   <<<(N_NODES + TB - 1) / TB, TB>>>();
    k_deg_scatter<<<(N_EDGES + TB - 1) / TB, TB>>>(ei);
    k_dinv       <<<(N_NODES + TB - 1) / TB, TB>>>();

    // layer 1: mma.sync bf16-split GEMM, fused q1/h1 epilogue
    gemm1_mma<<<(N_NODES + BM - 1) / BM, 256>>>(X, W1);
    k_scatter1 <<<(size_t)N_EDGES * 32 / TB, TB>>>(ei);
    k_relu_bias<<<((size_t)N_NODES * HID / 4 + TB - 1) / TB, TB>>>(b1);

    // layer 2: SIMT GEMM, fused q2/out epilogue
    {
        dim3 grid(CLS / 32, (N_NODES + 127) / 128);
        sgemm2_kernel<128, 32, 32, 8, 2><<<grid, 256>>>(p_h1, W2, p_q2, out,
                                                        p_dinv, N_NODES, CLS, HID);
    }
    k_scatter2  <<<((size_t)N_EDGES * 8 + TB - 1) / TB, TB>>>(ei, out);
    k_logsoftmax<<<(N_NODES + 7) / 8, 256>>>(b2, out);
}